// round 1
// baseline (speedup 1.0000x reference)
#include <cuda_runtime.h>
#include <math.h>

#define S_LEN  2048
#define DMODEL 4096
#define NHEADS 32
#define NKVH   8
#define HDIM   128
#define DFFN   16384

// ---------------- scratch (device globals; no allocation allowed) ----------------
__device__ float g_xn  [S_LEN * DMODEL];
__device__ float g_q   [S_LEN * DMODEL];
__device__ float g_k   [S_LEN * NKVH * HDIM];
__device__ float g_v   [S_LEN * NKVH * HDIM];
__device__ float g_attn[S_LEN * DMODEL];
__device__ float g_h   [S_LEN * DMODEL];
__device__ float g_x2  [S_LEN * DMODEL];
__device__ float g_gate[S_LEN * DFFN];
__device__ float g_up  [S_LEN * DFFN];

// ---------------- RMSNorm: one block per row (4096 cols, 256 threads) ----------------
__global__ __launch_bounds__(256) void rmsnorm_kernel(
    const float* __restrict__ x, const float* __restrict__ w, float* __restrict__ y)
{
    int row = blockIdx.x;
    const float* xr = x + (size_t)row * DMODEL;
    float* yr = y + (size_t)row * DMODEL;

    float4 vals[4];
    float ss = 0.f;
#pragma unroll
    for (int it = 0; it < 4; it++) {
        int idx = (threadIdx.x + it * 256) * 4;
        float4 v = *(const float4*)(xr + idx);
        vals[it] = v;
        ss += v.x*v.x + v.y*v.y + v.z*v.z + v.w*v.w;
    }
#pragma unroll
    for (int o = 16; o; o >>= 1) ss += __shfl_xor_sync(0xffffffffu, ss, o);

    __shared__ float red[8];
    if ((threadIdx.x & 31) == 0) red[threadIdx.x >> 5] = ss;
    __syncthreads();
    float tot = 0.f;
#pragma unroll
    for (int i = 0; i < 8; i++) tot += red[i];
    float inv = rsqrtf(tot * (1.f / DMODEL) + 1e-5f);

#pragma unroll
    for (int it = 0; it < 4; it++) {
        int idx = (threadIdx.x + it * 256) * 4;
        float4 v  = vals[it];
        float4 wv = *(const float4*)(w + idx);
        float4 r4;
        r4.x = v.x * inv * wv.x;
        r4.y = v.y * inv * wv.y;
        r4.z = v.z * inv * wv.z;
        r4.w = v.w * inv * wv.w;
        *(float4*)(yr + idx) = r4;
    }
}

// ---------------- fused RoPE + L2-norm (+optional score scaling), one warp per (token, head) ----------------
__global__ __launch_bounds__(256) void rope_l2_kernel(
    float* __restrict__ buf, int nheads,
    const float* __restrict__ cosb, const float* __restrict__ sinb, float scale)
{
    int wid  = (blockIdx.x * 256 + threadIdx.x) >> 5;
    int lane = threadIdx.x & 31;
    int s  = wid / nheads;
    int hh = wid % nheads;
    float* p = buf + (size_t)s * nheads * HDIM + hh * HDIM + lane * 4;
    float4 vv = *(float4*)p;

    float c0 = cosb[s * 64 + lane * 2],     s0 = sinb[s * 64 + lane * 2];
    float c1 = cosb[s * 64 + lane * 2 + 1], s1 = sinb[s * 64 + lane * 2 + 1];
    float o0 = vv.x * c0 - vv.y * s0;
    float o1 = vv.x * s0 + vv.y * c0;
    float o2 = vv.z * c1 - vv.w * s1;
    float o3 = vv.z * s1 + vv.w * c1;

    float ss = o0*o0 + o1*o1 + o2*o2 + o3*o3;
#pragma unroll
    for (int o = 16; o; o >>= 1) ss += __shfl_xor_sync(0xffffffffu, ss, o);
    float rr = rsqrtf(ss * (1.f / HDIM) + 1e-5f) * scale;

    vv.x = o0 * rr; vv.y = o1 * rr; vv.z = o2 * rr; vv.w = o3 * rr;
    *(float4*)p = vv;
}

// ---------------- SGEMM: C[M,N] = A[M,K] @ B[K,N] (+ addend), 128x128x8 tiles, 8x8/thread ----------------
__global__ __launch_bounds__(256, 2) void sgemm_kernel(
    const float* __restrict__ A, const float* __restrict__ B,
    float* __restrict__ C, const float* __restrict__ addend,
    int M, int N, int K)
{
    __shared__ float As[8][132];   // padded: conflict-free scatter + reads
    __shared__ float Bs[8][128];

    int tid = threadIdx.x;
    int tx = tid & 15, ty = tid >> 4;
    int bx = blockIdx.x, by = blockIdx.y;

    int arow = tid >> 1, acol = (tid & 1) * 4;
    int brow = tid >> 5, bcol = (tid & 31) * 4;
    const float* Aptr = A + (size_t)(by * 128 + arow) * K + acol;
    const float* Bptr = B + (size_t)brow * N + bx * 128 + bcol;

    float acc[8][8];
#pragma unroll
    for (int i = 0; i < 8; i++)
#pragma unroll
        for (int j = 0; j < 8; j++) acc[i][j] = 0.f;

    for (int k0 = 0; k0 < K; k0 += 8) {
        float4 a = *(const float4*)(Aptr + k0);
        float4 b = *(const float4*)(Bptr + (size_t)k0 * N);
        As[acol + 0][arow] = a.x;
        As[acol + 1][arow] = a.y;
        As[acol + 2][arow] = a.z;
        As[acol + 3][arow] = a.w;
        *(float4*)&Bs[brow][bcol] = b;
        __syncthreads();

#pragma unroll
        for (int kk = 0; kk < 8; kk++) {
            float ra[8], rb[8];
            *(float4*)&ra[0] = *(const float4*)&As[kk][ty * 4];
            *(float4*)&ra[4] = *(const float4*)&As[kk][64 + ty * 4];
            *(float4*)&rb[0] = *(const float4*)&Bs[kk][tx * 4];
            *(float4*)&rb[4] = *(const float4*)&Bs[kk][64 + tx * 4];
#pragma unroll
            for (int i = 0; i < 8; i++)
#pragma unroll
                for (int j = 0; j < 8; j++)
                    acc[i][j] = fmaf(ra[i], rb[j], acc[i][j]);
        }
        __syncthreads();
    }

#pragma unroll
    for (int ih = 0; ih < 2; ih++)
#pragma unroll
    for (int ii = 0; ii < 4; ii++) {
        int row = by * 128 + ih * 64 + ty * 4 + ii;
#pragma unroll
        for (int jh = 0; jh < 2; jh++) {
            int col = bx * 128 + jh * 64 + tx * 4;
            size_t idx = (size_t)row * N + col;
            float4 r4;
            r4.x = acc[ih * 4 + ii][jh * 4 + 0];
            r4.y = acc[ih * 4 + ii][jh * 4 + 1];
            r4.z = acc[ih * 4 + ii][jh * 4 + 2];
            r4.w = acc[ih * 4 + ii][jh * 4 + 3];
            if (addend) {
                float4 ad = *(const float4*)(addend + idx);
                r4.x += ad.x; r4.y += ad.y; r4.z += ad.z; r4.w += ad.w;
            }
            *(float4*)(C + idx) = r4;
        }
    }
}

// ---------------- causal flash attention, GQA (4 q-heads per kv-head) ----------------
// block = (q-tile of 64 rows, head). 256 threads: thread t -> row r=t>>2, group g=t&3.
// score cols per thread: c = g + 4*ci (ci<16); output dims per thread: g*4 + jj*16 + e.
__global__ __launch_bounds__(256) void flash_attn_kernel(
    const float* __restrict__ q, const float* __restrict__ k,
    const float* __restrict__ v, float* __restrict__ o)
{
    extern __shared__ float sm[];
    float* Qs = sm;               // 64*132
    float* Ks = Qs + 64 * 132;    // 64*132
    float* Vs = Ks + 64 * 132;    // 64*132
    float* Ps = Vs + 64 * 132;    // 64*68

    int qb = blockIdx.x, h = blockIdx.y;
    int kvh = h >> 2;
    int t = threadIdx.x;
    int r = t >> 2, g = t & 3;

    for (int i = t; i < 64 * 32; i += 256) {
        int rr = i >> 5, c4 = (i & 31) * 4;
        *(float4*)&Qs[rr * 132 + c4] =
            *(const float4*)(q + (size_t)(qb * 64 + rr) * DMODEL + h * HDIM + c4);
    }

    float O[32];
#pragma unroll
    for (int j = 0; j < 32; j++) O[j] = 0.f;
    float m = -1e30f, l = 0.f;

    for (int kb = 0; kb <= qb; kb++) {
        __syncthreads();  // protect prior PV reads of Ks/Vs/Ps
        for (int i = t; i < 64 * 32; i += 256) {
            int rr = i >> 5, c4 = (i & 31) * 4;
            size_t base = (size_t)(kb * 64 + rr) * (NKVH * HDIM) + kvh * HDIM + c4;
            *(float4*)&Ks[rr * 132 + c4] = *(const float4*)(k + base);
            *(float4*)&Vs[rr * 132 + c4] = *(const float4*)(v + base);
        }
        __syncthreads();

        float s16[16];
#pragma unroll
        for (int ci = 0; ci < 16; ci++) s16[ci] = 0.f;
        for (int d = 0; d < 128; d += 4) {
            float4 qv = *(const float4*)&Qs[r * 132 + d];
#pragma unroll
            for (int ci = 0; ci < 16; ci++) {
                float4 kv = *(const float4*)&Ks[(g + 4 * ci) * 132 + d];
                s16[ci] += qv.x * kv.x + qv.y * kv.y + qv.z * kv.z + qv.w * kv.w;
            }
        }
        if (kb == qb) {
#pragma unroll
            for (int ci = 0; ci < 16; ci++) {
                int c = g + 4 * ci;
                if (c > r) s16[ci] += -1e9f;   // same NEG as reference mask
            }
        }

        float tm = s16[0];
#pragma unroll
        for (int ci = 1; ci < 16; ci++) tm = fmaxf(tm, s16[ci]);
        tm = fmaxf(tm, __shfl_xor_sync(0xffffffffu, tm, 1));
        tm = fmaxf(tm, __shfl_xor_sync(0xffffffffu, tm, 2));
        float mnew = fmaxf(m, tm);
        float corr = __expf(m - mnew);

        float lsum = 0.f;
#pragma unroll
        for (int ci = 0; ci < 16; ci++) {
            float p = __expf(s16[ci] - mnew);
            Ps[r * 68 + g + 4 * ci] = p;
            lsum += p;
        }
        lsum += __shfl_xor_sync(0xffffffffu, lsum, 1);
        lsum += __shfl_xor_sync(0xffffffffu, lsum, 2);
        l = l * corr + lsum;
        m = mnew;
#pragma unroll
        for (int j = 0; j < 32; j++) O[j] *= corr;
        __syncthreads();  // Ps visible

        for (int c = 0; c < 64; c++) {
            float p = Ps[r * 68 + c];
#pragma unroll
            for (int jj = 0; jj < 8; jj++) {
                float4 vv = *(const float4*)&Vs[c * 132 + g * 4 + jj * 16];
                O[jj * 4 + 0] = fmaf(p, vv.x, O[jj * 4 + 0]);
                O[jj * 4 + 1] = fmaf(p, vv.y, O[jj * 4 + 1]);
                O[jj * 4 + 2] = fmaf(p, vv.z, O[jj * 4 + 2]);
                O[jj * 4 + 3] = fmaf(p, vv.w, O[jj * 4 + 3]);
            }
        }
    }

    float inv = 1.f / l;
    size_t orow = (size_t)(qb * 64 + r) * DMODEL + h * HDIM;
#pragma unroll
    for (int jj = 0; jj < 8; jj++) {
        float4 r4;
        r4.x = O[jj * 4 + 0] * inv;
        r4.y = O[jj * 4 + 1] * inv;
        r4.z = O[jj * 4 + 2] * inv;
        r4.w = O[jj * 4 + 3] * inv;
        *(float4*)(o + orow + g * 4 + jj * 16) = r4;
    }
}

// ---------------- SiLU(gate) * up, in place into gate ----------------
__global__ __launch_bounds__(256) void silu_mul_kernel(
    float* __restrict__ gate, const float* __restrict__ up)
{
    int i = blockIdx.x * 256 + threadIdx.x;
    float4 gv = ((float4*)gate)[i];
    float4 uv = ((const float4*)up)[i];
    gv.x = gv.x / (1.f + __expf(-gv.x)) * uv.x;
    gv.y = gv.y / (1.f + __expf(-gv.y)) * uv.y;
    gv.z = gv.z / (1.f + __expf(-gv.z)) * uv.z;
    gv.w = gv.w / (1.f + __expf(-gv.w)) * uv.w;
    ((float4*)gate)[i] = gv;
}

// ---------------- host launcher ----------------
extern "C" void kernel_launch(void* const* d_in, const int* in_sizes, int n_in,
                              void* d_out, int out_size)
{
    const float* hidden = (const float*)d_in[0];
    // d_in[1] = attn_mask (causal 0/-1e9) — implemented directly in-kernel
    const float* cosb  = (const float*)d_in[2];
    const float* sinb  = (const float*)d_in[3];
    const float* ln1   = (const float*)d_in[4];
    const float* wq    = (const float*)d_in[5];
    const float* wk    = (const float*)d_in[6];
    const float* wv    = (const float*)d_in[7];
    const float* wo    = (const float*)d_in[8];
    const float* ln2   = (const float*)d_in[9];
    const float* gatew = (const float*)d_in[10];
    const float* upw   = (const float*)d_in[11];
    const float* downw = (const float*)d_in[12];
    float* out = (float*)d_out;

    float *xn, *q, *k, *v, *attn, *h, *x2, *gate, *up;
    cudaGetSymbolAddress((void**)&xn,   g_xn);
    cudaGetSymbolAddress((void**)&q,    g_q);
    cudaGetSymbolAddress((void**)&k,    g_k);
    cudaGetSymbolAddress((void**)&v,    g_v);
    cudaGetSymbolAddress((void**)&attn, g_attn);
    cudaGetSymbolAddress((void**)&h,    g_h);
    cudaGetSymbolAddress((void**)&x2,   g_x2);
    cudaGetSymbolAddress((void**)&gate, g_gate);
    cudaGetSymbolAddress((void**)&up,   g_up);

    // 1) x = rmsnorm(hidden, ln1)
    rmsnorm_kernel<<<S_LEN, 256>>>(hidden, ln1, xn);

    // 2) q/k/v projections
    sgemm_kernel<<<dim3(DMODEL / 128, S_LEN / 128), 256>>>(xn, wq, q, nullptr, S_LEN, DMODEL, DMODEL);
    sgemm_kernel<<<dim3(NKVH * HDIM / 128, S_LEN / 128), 256>>>(xn, wk, k, nullptr, S_LEN, NKVH * HDIM, DMODEL);
    sgemm_kernel<<<dim3(NKVH * HDIM / 128, S_LEN / 128), 256>>>(xn, wv, v, nullptr, S_LEN, NKVH * HDIM, DMODEL);

    // 3) RoPE + L2-norm; fold score scaling (HD^-0.5) into q
    const float qscale = 0.08838834764831845f;  // 1/sqrt(128)
    rope_l2_kernel<<<S_LEN * NHEADS / 8, 256>>>(q, NHEADS, cosb, sinb, qscale);
    rope_l2_kernel<<<S_LEN * NKVH  / 8, 256>>>(k, NKVH,  cosb, sinb, 1.f);

    // 4) causal flash attention with GQA
    int smem = (3 * 64 * 132 + 64 * 68) * (int)sizeof(float);
    cudaFuncSetAttribute(flash_attn_kernel, cudaFuncAttributeMaxDynamicSharedMemorySize, smem);
    flash_attn_kernel<<<dim3(S_LEN / 64, NHEADS), 256, smem>>>(q, k, v, attn);

    // 5) h = hidden + attn @ wo
    sgemm_kernel<<<dim3(DMODEL / 128, S_LEN / 128), 256>>>(attn, wo, h, hidden, S_LEN, DMODEL, DMODEL);

    // 6) x2 = rmsnorm(h, ln2)
    rmsnorm_kernel<<<S_LEN, 256>>>(h, ln2, x2);

    // 7) FFN
    sgemm_kernel<<<dim3(DFFN / 128, S_LEN / 128), 256>>>(x2, gatew, gate, nullptr, S_LEN, DFFN, DMODEL);
    sgemm_kernel<<<dim3(DFFN / 128, S_LEN / 128), 256>>>(x2, upw,   up,   nullptr, S_LEN, DFFN, DMODEL);
    silu_mul_kernel<<<(S_LEN * DFFN) / 4 / 256, 256>>>(gate, up);

    // 8) out = h + (silu(gate)*up) @ down
    sgemm_kernel<<<dim3(DMODEL / 128, S_LEN / 128), 256>>>(gate, downw, out, h, S_LEN, DMODEL, DFFN);
}

// round 3
// speedup vs baseline: 2.4967x; 2.4967x over previous
#include <cuda_runtime.h>
#include <cuda_bf16.h>
#include <math.h>
#include <stdint.h>

#define S_LEN  2048
#define DMODEL 4096
#define NHEADS 32
#define NKVH   8
#define HDIM   128
#define DFFN   16384

// ================= low-level helpers (base sm_103 ISA only: ldmatrix/mma/cp.async) =================
__device__ __forceinline__ uint32_t smem_u32(const void* p) {
    uint32_t a;
    asm("{ .reg .u64 t; cvta.to.shared.u64 t, %1; cvt.u32.u64 %0, t; }" : "=r"(a) : "l"(p));
    return a;
}

__device__ __forceinline__ void cp_async16(uint32_t dst, const void* src) {
    asm volatile("cp.async.cg.shared.global [%0], [%1], 16;" :: "r"(dst), "l"(src));
}
#define CP_COMMIT() asm volatile("cp.async.commit_group;" ::: "memory")
#define CP_WAIT1()  asm volatile("cp.async.wait_group 1;" ::: "memory")

__device__ __forceinline__ void ldsm4(uint32_t* r, uint32_t addr) {
    asm volatile("ldmatrix.sync.aligned.m8n8.x4.shared.b16 {%0,%1,%2,%3}, [%4];"
        : "=r"(r[0]), "=r"(r[1]), "=r"(r[2]), "=r"(r[3]) : "r"(addr));
}

__device__ __forceinline__ void mma16816(float* d, const uint32_t* a, uint32_t b0, uint32_t b1) {
    asm volatile("mma.sync.aligned.m16n8k16.row.col.f32.bf16.bf16.f32 "
        "{%0,%1,%2,%3}, {%4,%5,%6,%7}, {%8,%9}, {%0,%1,%2,%3};"
        : "+f"(d[0]), "+f"(d[1]), "+f"(d[2]), "+f"(d[3])
        : "r"(a[0]), "r"(a[1]), "r"(a[2]), "r"(a[3]), "r"(b0), "r"(b1));
}

// ================= scratch (device globals; no allocation allowed) =================
__device__ float g_xn  [S_LEN * DMODEL];
__device__ float g_q   [S_LEN * DMODEL];
__device__ float g_k   [S_LEN * NKVH * HDIM];
__device__ float g_v   [S_LEN * NKVH * HDIM];
__device__ float g_attn[S_LEN * DMODEL];
__device__ float g_h   [S_LEN * DMODEL];
__device__ float g_x2  [S_LEN * DMODEL];
__device__ float g_gate[S_LEN * DFFN];
__device__ float g_up  [S_LEN * DFFN];

// bf16 hi/lo transposed weights: W^T [N, K]
__device__ __nv_bfloat16 g_wqT_h[DMODEL * DMODEL],        g_wqT_l[DMODEL * DMODEL];
__device__ __nv_bfloat16 g_wkT_h[NKVH * HDIM * DMODEL],   g_wkT_l[NKVH * HDIM * DMODEL];
__device__ __nv_bfloat16 g_wvT_h[NKVH * HDIM * DMODEL],   g_wvT_l[NKVH * HDIM * DMODEL];
__device__ __nv_bfloat16 g_woT_h[DMODEL * DMODEL],        g_woT_l[DMODEL * DMODEL];
__device__ __nv_bfloat16 g_gwT_h[DFFN * DMODEL],          g_gwT_l[DFFN * DMODEL];
__device__ __nv_bfloat16 g_uwT_h[DFFN * DMODEL],          g_uwT_l[DFFN * DMODEL];
__device__ __nv_bfloat16 g_dwT_h[DMODEL * DFFN],          g_dwT_l[DMODEL * DFFN];

// bf16 hi/lo activations
__device__ __nv_bfloat16 g_xn_h [S_LEN * DMODEL], g_xn_l [S_LEN * DMODEL];
__device__ __nv_bfloat16 g_at_h [S_LEN * DMODEL], g_at_l [S_LEN * DMODEL];
__device__ __nv_bfloat16 g_x2_h [S_LEN * DMODEL], g_x2_l [S_LEN * DMODEL];
__device__ __nv_bfloat16 g_ga_h [S_LEN * DFFN],   g_ga_l [S_LEN * DFFN];

// ================= RMSNorm =================
__global__ __launch_bounds__(256) void rmsnorm_kernel(
    const float* __restrict__ x, const float* __restrict__ w, float* __restrict__ y)
{
    int row = blockIdx.x;
    const float* xr = x + (size_t)row * DMODEL;
    float* yr = y + (size_t)row * DMODEL;

    float4 vals[4];
    float ss = 0.f;
#pragma unroll
    for (int it = 0; it < 4; it++) {
        int idx = (threadIdx.x + it * 256) * 4;
        float4 v = *(const float4*)(xr + idx);
        vals[it] = v;
        ss += v.x*v.x + v.y*v.y + v.z*v.z + v.w*v.w;
    }
#pragma unroll
    for (int o = 16; o; o >>= 1) ss += __shfl_xor_sync(0xffffffffu, ss, o);

    __shared__ float red[8];
    if ((threadIdx.x & 31) == 0) red[threadIdx.x >> 5] = ss;
    __syncthreads();
    float tot = 0.f;
#pragma unroll
    for (int i = 0; i < 8; i++) tot += red[i];
    float inv = rsqrtf(tot * (1.f / DMODEL) + 1e-5f);

#pragma unroll
    for (int it = 0; it < 4; it++) {
        int idx = (threadIdx.x + it * 256) * 4;
        float4 v  = vals[it];
        float4 wv = *(const float4*)(w + idx);
        float4 r4;
        r4.x = v.x * inv * wv.x;
        r4.y = v.y * inv * wv.y;
        r4.z = v.z * inv * wv.z;
        r4.w = v.w * inv * wv.w;
        *(float4*)(yr + idx) = r4;
    }
}

// ================= RoPE + L2-norm =================
__global__ __launch_bounds__(256) void rope_l2_kernel(
    float* __restrict__ buf, int nheads,
    const float* __restrict__ cosb, const float* __restrict__ sinb, float scale)
{
    int wid  = (blockIdx.x * 256 + threadIdx.x) >> 5;
    int lane = threadIdx.x & 31;
    int s  = wid / nheads;
    int hh = wid % nheads;
    float* p = buf + (size_t)s * nheads * HDIM + hh * HDIM + lane * 4;
    float4 vv = *(float4*)p;

    float c0 = cosb[s * 64 + lane * 2],     s0 = sinb[s * 64 + lane * 2];
    float c1 = cosb[s * 64 + lane * 2 + 1], s1 = sinb[s * 64 + lane * 2 + 1];
    float o0 = vv.x * c0 - vv.y * s0;
    float o1 = vv.x * s0 + vv.y * c0;
    float o2 = vv.z * c1 - vv.w * s1;
    float o3 = vv.z * s1 + vv.w * c1;

    float ss = o0*o0 + o1*o1 + o2*o2 + o3*o3;
#pragma unroll
    for (int o = 16; o; o >>= 1) ss += __shfl_xor_sync(0xffffffffu, ss, o);
    float rr = rsqrtf(ss * (1.f / HDIM) + 1e-5f) * scale;

    vv.x = o0 * rr; vv.y = o1 * rr; vv.z = o2 * rr; vv.w = o3 * rr;
    *(float4*)p = vv;
}

// ================= transpose + bf16 hi/lo split: in[K,N] fp32 -> hi/lo [N,K] bf16 =================
__global__ __launch_bounds__(256) void transpose_split_kernel(
    const float* __restrict__ in, __nv_bfloat16* __restrict__ hi, __nv_bfloat16* __restrict__ lo,
    int K, int N)
{
    __shared__ float s[64][65];
    int r0 = blockIdx.y * 64, c0 = blockIdx.x * 64;
#pragma unroll
    for (int i = 0; i < 16; i++) {
        int idx = threadIdx.x + i * 256;
        int lr = idx >> 6, lc = idx & 63;
        s[lr][lc] = in[(size_t)(r0 + lr) * N + c0 + lc];
    }
    __syncthreads();
#pragma unroll
    for (int i = 0; i < 16; i++) {
        int idx = threadIdx.x + i * 256;
        int lr = idx >> 6, lc = idx & 63;
        float v = s[lc][lr];
        __nv_bfloat16 h = __float2bfloat16(v);
        __nv_bfloat16 l = __float2bfloat16(v - __bfloat162float(h));
        size_t o = (size_t)(c0 + lr) * K + (r0 + lc);
        hi[o] = h; lo[o] = l;
    }
}

// ================= elementwise bf16 hi/lo split =================
__global__ __launch_bounds__(256) void split_kernel(
    const float* __restrict__ x, __nv_bfloat16* __restrict__ hi, __nv_bfloat16* __restrict__ lo)
{
    size_t i = (size_t)(blockIdx.x) * 256 + threadIdx.x;
    float4 v = ((const float4*)x)[i];
    __nv_bfloat16 h0 = __float2bfloat16(v.x), h1 = __float2bfloat16(v.y);
    __nv_bfloat16 h2 = __float2bfloat16(v.z), h3 = __float2bfloat16(v.w);
    __nv_bfloat16 l0 = __float2bfloat16(v.x - __bfloat162float(h0));
    __nv_bfloat16 l1 = __float2bfloat16(v.y - __bfloat162float(h1));
    __nv_bfloat16 l2 = __float2bfloat16(v.z - __bfloat162float(h2));
    __nv_bfloat16 l3 = __float2bfloat16(v.w - __bfloat162float(h3));
    uint2 hv, lv;
    hv.x = (uint32_t)__bfloat16_as_ushort(h0) | ((uint32_t)__bfloat16_as_ushort(h1) << 16);
    hv.y = (uint32_t)__bfloat16_as_ushort(h2) | ((uint32_t)__bfloat16_as_ushort(h3) << 16);
    lv.x = (uint32_t)__bfloat16_as_ushort(l0) | ((uint32_t)__bfloat16_as_ushort(l1) << 16);
    lv.y = (uint32_t)__bfloat16_as_ushort(l2) | ((uint32_t)__bfloat16_as_ushort(l3) << 16);
    ((uint2*)hi)[i] = hv;
    ((uint2*)lo)[i] = lv;
}

// ================= HMMA split-bf16 GEMM =================
// C[M,N] = A[M,K] @ B^T[N,K]  (3-term hi/lo), optional fused addend.
// CTA 128x128, K-chunk 64, 3-stage cp.async ring, 8 warps @ 64x32.
// Smem tile layout per chunk: 128 rows x 128B (SW128 xor swizzle at 16B granularity).
#define TCG_STAGE_BYTES 65536       // 4 tiles x 16KB (Ahi, Alo, Bhi, Blo)
#define TCG_NSTAGE 3
#define TCG_SMEM (TCG_NSTAGE * TCG_STAGE_BYTES)

__global__ __launch_bounds__(256, 1) void tc_gemm_kernel(
    const __nv_bfloat16* __restrict__ Ahi, const __nv_bfloat16* __restrict__ Alo,
    const __nv_bfloat16* __restrict__ Bhi, const __nv_bfloat16* __restrict__ Blo,
    float* __restrict__ C, const float* __restrict__ addend, int M, int N, int K)
{
    extern __shared__ char sm[];
    uint32_t sbase = smem_u32(sm);
    int tid = threadIdx.x, lane = tid & 31, wid = tid >> 5;
    int warp_m = wid & 1, warp_n = wid >> 1;     // 2 x 4 warp grid
    int bx = blockIdx.x, by = blockIdx.y;

    const __nv_bfloat16* srcA[2] = { Ahi + (size_t)(by * 128) * K, Alo + (size_t)(by * 128) * K };
    const __nv_bfloat16* srcB[2] = { Bhi + (size_t)(bx * 128) * K, Blo + (size_t)(bx * 128) * K };

    int nchunk = K >> 6;

    // per-thread cp.async geometry: 4 units of 16B per 16KB tile
    int ldrow = tid >> 3;            // 0..31 (advance by 32 rows per iter)
    int ldc16 = tid & 7;             // 16B unit within 128B row

    auto load_stage = [&](int stg, int c) {
        uint32_t dst0 = sbase + stg * TCG_STAGE_BYTES;
        int kc = c << 6;
#pragma unroll
        for (int hl = 0; hl < 2; hl++) {
            const __nv_bfloat16* sa = srcA[hl] + kc;
            const __nv_bfloat16* sb = srcB[hl] + kc;
            uint32_t da = dst0 + hl * 16384;
            uint32_t db = dst0 + 32768 + hl * 16384;
#pragma unroll
            for (int i = 0; i < 4; i++) {
                int row = ldrow + i * 32;
                uint32_t sw = row * 128 + ((ldc16 ^ (row & 7)) << 4);
                cp_async16(da + sw, sa + (size_t)row * K + ldc16 * 8);
                cp_async16(db + sw, sb + (size_t)row * K + ldc16 * 8);
            }
        }
    };

    load_stage(0, 0); CP_COMMIT();
    load_stage(1, 1); CP_COMMIT();

    float acc[4][4][4];
#pragma unroll
    for (int a = 0; a < 4; a++)
#pragma unroll
        for (int b = 0; b < 4; b++)
#pragma unroll
            for (int f = 0; f < 4; f++) acc[a][b][f] = 0.f;

    // ldmatrix per-lane row/half geometry
    int a_r   = warp_m * 64 + (lane & 15);     // + mb*16
    int a_kh  = lane >> 4;                      // 16B half within k16
    int b_r   = warp_n * 32 + (lane & 7) + ((lane >> 4) << 3);  // + nbh*16
    int b_kh  = (lane >> 3) & 1;

    for (int c = 0; c < nchunk; c++) {
        CP_WAIT1();
        __syncthreads();
        if (c + 2 < nchunk) load_stage((c + 2) % TCG_NSTAGE, c + 2);
        CP_COMMIT();

        uint32_t st = sbase + (c % TCG_NSTAGE) * TCG_STAGE_BYTES;
#pragma unroll
        for (int kk = 0; kk < 4; kk++) {
            int c16 = kk * 2;
            uint32_t ah[4][4], al[4][4], bh[2][4], bl[2][4];
#pragma unroll
            for (int mb = 0; mb < 4; mb++) {
                int r = a_r + mb * 16;
                uint32_t off = r * 128 + (((c16 + a_kh) ^ (r & 7)) << 4);
                ldsm4(ah[mb], st + off);
                ldsm4(al[mb], st + 16384 + off);
            }
#pragma unroll
            for (int nb = 0; nb < 2; nb++) {
                int r = b_r + nb * 16;
                uint32_t off = r * 128 + (((c16 + b_kh) ^ (r & 7)) << 4);
                ldsm4(bh[nb], st + 32768 + off);
                ldsm4(bl[nb], st + 49152 + off);
            }
#pragma unroll
            for (int mb = 0; mb < 4; mb++)
#pragma unroll
                for (int nb = 0; nb < 4; nb++) {
                    uint32_t b0h = bh[nb >> 1][(nb & 1) * 2], b1h = bh[nb >> 1][(nb & 1) * 2 + 1];
                    uint32_t b0l = bl[nb >> 1][(nb & 1) * 2], b1l = bl[nb >> 1][(nb & 1) * 2 + 1];
                    mma16816(acc[mb][nb], ah[mb], b0h, b1h);
                    mma16816(acc[mb][nb], ah[mb], b0l, b1l);
                    mma16816(acc[mb][nb], al[mb], b0h, b1h);
                }
        }
        __syncthreads();
    }

    // epilogue: frag rows m = lane>>2 (+8), cols n = (lane&3)*2
#pragma unroll
    for (int mb = 0; mb < 4; mb++) {
        int mrow = by * 128 + warp_m * 64 + mb * 16 + (lane >> 2);
#pragma unroll
        for (int nb = 0; nb < 4; nb++) {
            int ncol = bx * 128 + warp_n * 32 + nb * 8 + (lane & 3) * 2;
            size_t i0 = (size_t)mrow * N + ncol;
            size_t i1 = (size_t)(mrow + 8) * N + ncol;
            float2 r0 = make_float2(acc[mb][nb][0], acc[mb][nb][1]);
            float2 r1 = make_float2(acc[mb][nb][2], acc[mb][nb][3]);
            if (addend) {
                float2 a0 = *(const float2*)(addend + i0);
                float2 a1 = *(const float2*)(addend + i1);
                r0.x += a0.x; r0.y += a0.y;
                r1.x += a1.x; r1.y += a1.y;
            }
            *(float2*)(C + i0) = r0;
            *(float2*)(C + i1) = r1;
        }
    }
}

// ================= causal flash attention, GQA =================
__global__ __launch_bounds__(256) void flash_attn_kernel(
    const float* __restrict__ q, const float* __restrict__ k,
    const float* __restrict__ v, float* __restrict__ o)
{
    extern __shared__ float smf[];
    float* Qs = smf;
    float* Ks = Qs + 64 * 132;
    float* Vs = Ks + 64 * 132;
    float* Ps = Vs + 64 * 132;

    int qb = blockIdx.x, h = blockIdx.y;
    int kvh = h >> 2;
    int t = threadIdx.x;
    int r = t >> 2, g = t & 3;

    for (int i = t; i < 64 * 32; i += 256) {
        int rr = i >> 5, c4 = (i & 31) * 4;
        *(float4*)&Qs[rr * 132 + c4] =
            *(const float4*)(q + (size_t)(qb * 64 + rr) * DMODEL + h * HDIM + c4);
    }

    float O[32];
#pragma unroll
    for (int j = 0; j < 32; j++) O[j] = 0.f;
    float m = -1e30f, l = 0.f;

    for (int kb = 0; kb <= qb; kb++) {
        __syncthreads();
        for (int i = t; i < 64 * 32; i += 256) {
            int rr = i >> 5, c4 = (i & 31) * 4;
            size_t base = (size_t)(kb * 64 + rr) * (NKVH * HDIM) + kvh * HDIM + c4;
            *(float4*)&Ks[rr * 132 + c4] = *(const float4*)(k + base);
            *(float4*)&Vs[rr * 132 + c4] = *(const float4*)(v + base);
        }
        __syncthreads();

        float s16[16];
#pragma unroll
        for (int ci = 0; ci < 16; ci++) s16[ci] = 0.f;
        for (int d = 0; d < 128; d += 4) {
            float4 qv = *(const float4*)&Qs[r * 132 + d];
#pragma unroll
            for (int ci = 0; ci < 16; ci++) {
                float4 kv = *(const float4*)&Ks[(g + 4 * ci) * 132 + d];
                s16[ci] += qv.x * kv.x + qv.y * kv.y + qv.z * kv.z + qv.w * kv.w;
            }
        }
        if (kb == qb) {
#pragma unroll
            for (int ci = 0; ci < 16; ci++) {
                int c = g + 4 * ci;
                if (c > r) s16[ci] += -1e9f;
            }
        }

        float tm = s16[0];
#pragma unroll
        for (int ci = 1; ci < 16; ci++) tm = fmaxf(tm, s16[ci]);
        tm = fmaxf(tm, __shfl_xor_sync(0xffffffffu, tm, 1));
        tm = fmaxf(tm, __shfl_xor_sync(0xffffffffu, tm, 2));
        float mnew = fmaxf(m, tm);
        float corr = __expf(m - mnew);

        float lsum = 0.f;
#pragma unroll
        for (int ci = 0; ci < 16; ci++) {
            float p = __expf(s16[ci] - mnew);
            Ps[r * 68 + g + 4 * ci] = p;
            lsum += p;
        }
        lsum += __shfl_xor_sync(0xffffffffu, lsum, 1);
        lsum += __shfl_xor_sync(0xffffffffu, lsum, 2);
        l = l * corr + lsum;
        m = mnew;
#pragma unroll
        for (int j = 0; j < 32; j++) O[j] *= corr;
        __syncthreads();

        for (int c = 0; c < 64; c++) {
            float p = Ps[r * 68 + c];
#pragma unroll
            for (int jj = 0; jj < 8; jj++) {
                float4 vv = *(const float4*)&Vs[c * 132 + g * 4 + jj * 16];
                O[jj * 4 + 0] = fmaf(p, vv.x, O[jj * 4 + 0]);
                O[jj * 4 + 1] = fmaf(p, vv.y, O[jj * 4 + 1]);
                O[jj * 4 + 2] = fmaf(p, vv.z, O[jj * 4 + 2]);
                O[jj * 4 + 3] = fmaf(p, vv.w, O[jj * 4 + 3]);
            }
        }
    }

    float inv = 1.f / l;
    size_t orow = (size_t)(qb * 64 + r) * DMODEL + h * HDIM;
#pragma unroll
    for (int jj = 0; jj < 8; jj++) {
        float4 r4;
        r4.x = O[jj * 4 + 0] * inv;
        r4.y = O[jj * 4 + 1] * inv;
        r4.z = O[jj * 4 + 2] * inv;
        r4.w = O[jj * 4 + 3] * inv;
        *(float4*)(o + orow + g * 4 + jj * 16) = r4;
    }
}

// ================= SiLU(gate) * up =================
__global__ __launch_bounds__(256) void silu_mul_kernel(
    float* __restrict__ gate, const float* __restrict__ up)
{
    int i = blockIdx.x * 256 + threadIdx.x;
    float4 gv = ((float4*)gate)[i];
    float4 uv = ((const float4*)up)[i];
    gv.x = gv.x / (1.f + __expf(-gv.x)) * uv.x;
    gv.y = gv.y / (1.f + __expf(-gv.y)) * uv.y;
    gv.z = gv.z / (1.f + __expf(-gv.z)) * uv.z;
    gv.w = gv.w / (1.f + __expf(-gv.w)) * uv.w;
    ((float4*)gate)[i] = gv;
}

// ================= host launcher =================
extern "C" void kernel_launch(void* const* d_in, const int* in_sizes, int n_in,
                              void* d_out, int out_size)
{
    const float* hidden = (const float*)d_in[0];
    const float* cosb  = (const float*)d_in[2];
    const float* sinb  = (const float*)d_in[3];
    const float* ln1   = (const float*)d_in[4];
    const float* wq    = (const float*)d_in[5];
    const float* wk    = (const float*)d_in[6];
    const float* wv    = (const float*)d_in[7];
    const float* wo    = (const float*)d_in[8];
    const float* ln2   = (const float*)d_in[9];
    const float* gatew = (const float*)d_in[10];
    const float* upw   = (const float*)d_in[11];
    const float* downw = (const float*)d_in[12];
    float* out = (float*)d_out;

    float *xn, *q, *k, *v, *attn, *h, *x2, *gate, *up;
    cudaGetSymbolAddress((void**)&xn,   g_xn);
    cudaGetSymbolAddress((void**)&q,    g_q);
    cudaGetSymbolAddress((void**)&k,    g_k);
    cudaGetSymbolAddress((void**)&v,    g_v);
    cudaGetSymbolAddress((void**)&attn, g_attn);
    cudaGetSymbolAddress((void**)&h,    g_h);
    cudaGetSymbolAddress((void**)&x2,   g_x2);
    cudaGetSymbolAddress((void**)&gate, g_gate);
    cudaGetSymbolAddress((void**)&up,   g_up);

    __nv_bfloat16 *wqTh,*wqTl,*wkTh,*wkTl,*wvTh,*wvTl,*woTh,*woTl,*gwTh,*gwTl,*uwTh,*uwTl,*dwTh,*dwTl;
    cudaGetSymbolAddress((void**)&wqTh, g_wqT_h); cudaGetSymbolAddress((void**)&wqTl, g_wqT_l);
    cudaGetSymbolAddress((void**)&wkTh, g_wkT_h); cudaGetSymbolAddress((void**)&wkTl, g_wkT_l);
    cudaGetSymbolAddress((void**)&wvTh, g_wvT_h); cudaGetSymbolAddress((void**)&wvTl, g_wvT_l);
    cudaGetSymbolAddress((void**)&woTh, g_woT_h); cudaGetSymbolAddress((void**)&woTl, g_woT_l);
    cudaGetSymbolAddress((void**)&gwTh, g_gwT_h); cudaGetSymbolAddress((void**)&gwTl, g_gwT_l);
    cudaGetSymbolAddress((void**)&uwTh, g_uwT_h); cudaGetSymbolAddress((void**)&uwTl, g_uwT_l);
    cudaGetSymbolAddress((void**)&dwTh, g_dwT_h); cudaGetSymbolAddress((void**)&dwTl, g_dwT_l);

    __nv_bfloat16 *xnh,*xnl,*ath,*atl,*x2h,*x2l,*gah,*gal;
    cudaGetSymbolAddress((void**)&xnh, g_xn_h); cudaGetSymbolAddress((void**)&xnl, g_xn_l);
    cudaGetSymbolAddress((void**)&ath, g_at_h); cudaGetSymbolAddress((void**)&atl, g_at_l);
    cudaGetSymbolAddress((void**)&x2h, g_x2_h); cudaGetSymbolAddress((void**)&x2l, g_x2_l);
    cudaGetSymbolAddress((void**)&gah, g_ga_h); cudaGetSymbolAddress((void**)&gal, g_ga_l);

    cudaFuncSetAttribute(tc_gemm_kernel, cudaFuncAttributeMaxDynamicSharedMemorySize, TCG_SMEM);

    // ---- weight transposes + hi/lo splits (in[K,N] -> out[N,K]) ----
    transpose_split_kernel<<<dim3(DMODEL/64, DMODEL/64), 256>>>(wq, wqTh, wqTl, DMODEL, DMODEL);
    transpose_split_kernel<<<dim3(NKVH*HDIM/64, DMODEL/64), 256>>>(wk, wkTh, wkTl, DMODEL, NKVH*HDIM);
    transpose_split_kernel<<<dim3(NKVH*HDIM/64, DMODEL/64), 256>>>(wv, wvTh, wvTl, DMODEL, NKVH*HDIM);
    transpose_split_kernel<<<dim3(DMODEL/64, DMODEL/64), 256>>>(wo, woTh, woTl, DMODEL, DMODEL);
    transpose_split_kernel<<<dim3(DFFN/64, DMODEL/64), 256>>>(gatew, gwTh, gwTl, DMODEL, DFFN);
    transpose_split_kernel<<<dim3(DFFN/64, DMODEL/64), 256>>>(upw,   uwTh, uwTl, DMODEL, DFFN);
    transpose_split_kernel<<<dim3(DMODEL/64, DFFN/64), 256>>>(downw, dwTh, dwTl, DFFN, DMODEL);

    // 1) x = rmsnorm(hidden, ln1); split
    rmsnorm_kernel<<<S_LEN, 256>>>(hidden, ln1, xn);
    split_kernel<<<(S_LEN * DMODEL) / 4 / 256, 256>>>(xn, xnh, xnl);

    // 2) q/k/v projections (HMMA)
    tc_gemm_kernel<<<dim3(DMODEL/128, S_LEN/128), 256, TCG_SMEM>>>(xnh, xnl, wqTh, wqTl, q, nullptr, S_LEN, DMODEL, DMODEL);
    tc_gemm_kernel<<<dim3(NKVH*HDIM/128, S_LEN/128), 256, TCG_SMEM>>>(xnh, xnl, wkTh, wkTl, k, nullptr, S_LEN, NKVH*HDIM, DMODEL);
    tc_gemm_kernel<<<dim3(NKVH*HDIM/128, S_LEN/128), 256, TCG_SMEM>>>(xnh, xnl, wvTh, wvTl, v, nullptr, S_LEN, NKVH*HDIM, DMODEL);

    // 3) RoPE + L2-norm; fold HD^-0.5 into q
    const float qscale = 0.08838834764831845f;
    rope_l2_kernel<<<S_LEN * NHEADS / 8, 256>>>(q, NHEADS, cosb, sinb, qscale);
    rope_l2_kernel<<<S_LEN * NKVH  / 8, 256>>>(k, NKVH,  cosb, sinb, 1.f);

    // 4) causal flash attention (fp32)
    int fa_smem = (3 * 64 * 132 + 64 * 68) * (int)sizeof(float);
    cudaFuncSetAttribute(flash_attn_kernel, cudaFuncAttributeMaxDynamicSharedMemorySize, fa_smem);
    flash_attn_kernel<<<dim3(S_LEN / 64, NHEADS), 256, fa_smem>>>(q, k, v, attn);

    // 5) h = hidden + attn @ wo
    split_kernel<<<(S_LEN * DMODEL) / 4 / 256, 256>>>(attn, ath, atl);
    tc_gemm_kernel<<<dim3(DMODEL/128, S_LEN/128), 256, TCG_SMEM>>>(ath, atl, woTh, woTl, h, hidden, S_LEN, DMODEL, DMODEL);

    // 6) x2 = rmsnorm(h, ln2); split
    rmsnorm_kernel<<<S_LEN, 256>>>(h, ln2, x2);
    split_kernel<<<(S_LEN * DMODEL) / 4 / 256, 256>>>(x2, x2h, x2l);

    // 7) FFN up/gate
    tc_gemm_kernel<<<dim3(DFFN/128, S_LEN/128), 256, TCG_SMEM>>>(x2h, x2l, gwTh, gwTl, gate, nullptr, S_LEN, DFFN, DMODEL);
    tc_gemm_kernel<<<dim3(DFFN/128, S_LEN/128), 256, TCG_SMEM>>>(x2h, x2l, uwTh, uwTl, up,   nullptr, S_LEN, DFFN, DMODEL);
    silu_mul_kernel<<<(S_LEN * DFFN) / 4 / 256, 256>>>(gate, up);
    split_kernel<<<(S_LEN * DFFN) / 4 / 256, 256>>>(gate, gah, gal);

    // 8) out = h + act @ down
    tc_gemm_kernel<<<dim3(DMODEL/128, S_LEN/128), 256, TCG_SMEM>>>(gah, gal, dwTh, dwTl, out, h, S_LEN, DMODEL, DFFN);
}

// round 4
// speedup vs baseline: 3.2053x; 1.2838x over previous
#include <cuda_runtime.h>
#include <cuda_bf16.h>
#include <math.h>
#include <stdint.h>

#define S_LEN  2048
#define DMODEL 4096
#define NHEADS 32
#define NKVH   8
#define HDIM   128
#define DFFN   16384

// ================= low-level helpers (base sm_103 ISA: ldmatrix/mma/cp.async) =================
__device__ __forceinline__ uint32_t smem_u32(const void* p) {
    uint32_t a;
    asm("{ .reg .u64 t; cvta.to.shared.u64 t, %1; cvt.u32.u64 %0, t; }" : "=r"(a) : "l"(p));
    return a;
}
__device__ __forceinline__ void cp_async16(uint32_t dst, const void* src) {
    asm volatile("cp.async.cg.shared.global [%0], [%1], 16;" :: "r"(dst), "l"(src));
}
#define CP_COMMIT() asm volatile("cp.async.commit_group;" ::: "memory")
#define CP_WAIT1()  asm volatile("cp.async.wait_group 1;" ::: "memory")

__device__ __forceinline__ void ldsm4(uint32_t* r, uint32_t addr) {
    asm volatile("ldmatrix.sync.aligned.m8n8.x4.shared.b16 {%0,%1,%2,%3}, [%4];"
        : "=r"(r[0]), "=r"(r[1]), "=r"(r[2]), "=r"(r[3]) : "r"(addr));
}
__device__ __forceinline__ void ldsm4t(uint32_t* r, uint32_t addr) {
    asm volatile("ldmatrix.sync.aligned.m8n8.x4.trans.shared.b16 {%0,%1,%2,%3}, [%4];"
        : "=r"(r[0]), "=r"(r[1]), "=r"(r[2]), "=r"(r[3]) : "r"(addr));
}
__device__ __forceinline__ void mma16816(float* d, const uint32_t* a, uint32_t b0, uint32_t b1) {
    asm volatile("mma.sync.aligned.m16n8k16.row.col.f32.bf16.bf16.f32 "
        "{%0,%1,%2,%3}, {%4,%5,%6,%7}, {%8,%9}, {%0,%1,%2,%3};"
        : "+f"(d[0]), "+f"(d[1]), "+f"(d[2]), "+f"(d[3])
        : "r"(a[0]), "r"(a[1]), "r"(a[2]), "r"(a[3]), "r"(b0), "r"(b1));
}

__device__ __forceinline__ uint32_t packbf(float a, float b) {
    return (uint32_t)__bfloat16_as_ushort(__float2bfloat16(a)) |
           ((uint32_t)__bfloat16_as_ushort(__float2bfloat16(b)) << 16);
}
__device__ __forceinline__ void split2(float a, float b, uint32_t& hi, uint32_t& lo) {
    __nv_bfloat16 ha = __float2bfloat16(a), hb = __float2bfloat16(b);
    hi = (uint32_t)__bfloat16_as_ushort(ha) | ((uint32_t)__bfloat16_as_ushort(hb) << 16);
    lo = packbf(a - __bfloat162float(ha), b - __bfloat162float(hb));
}

// ================= scratch (device globals; no allocation allowed) =================
__device__ float g_q   [S_LEN * DMODEL];
__device__ float g_k   [S_LEN * NKVH * HDIM];
__device__ float g_h   [S_LEN * DMODEL];
__device__ float g_gate[S_LEN * DFFN];
__device__ float g_up  [S_LEN * DFFN];

// bf16 hi/lo transposed weights: W^T [N, K]
__device__ __nv_bfloat16 g_wqT_h[DMODEL * DMODEL],        g_wqT_l[DMODEL * DMODEL];
__device__ __nv_bfloat16 g_wkT_h[NKVH * HDIM * DMODEL],   g_wkT_l[NKVH * HDIM * DMODEL];
__device__ __nv_bfloat16 g_wvT_h[NKVH * HDIM * DMODEL],   g_wvT_l[NKVH * HDIM * DMODEL];
__device__ __nv_bfloat16 g_woT_h[DMODEL * DMODEL],        g_woT_l[DMODEL * DMODEL];
__device__ __nv_bfloat16 g_gwT_h[DFFN * DMODEL],          g_gwT_l[DFFN * DMODEL];
__device__ __nv_bfloat16 g_uwT_h[DFFN * DMODEL],          g_uwT_l[DFFN * DMODEL];
__device__ __nv_bfloat16 g_dwT_h[DMODEL * DFFN],          g_dwT_l[DMODEL * DFFN];

// bf16 hi/lo activations
__device__ __nv_bfloat16 g_xn_h [S_LEN * DMODEL],       g_xn_l [S_LEN * DMODEL];
__device__ __nv_bfloat16 g_qh  [S_LEN * DMODEL],        g_ql  [S_LEN * DMODEL];
__device__ __nv_bfloat16 g_kh  [S_LEN * NKVH * HDIM],   g_kl  [S_LEN * NKVH * HDIM];
__device__ __nv_bfloat16 g_vh  [S_LEN * NKVH * HDIM],   g_vl  [S_LEN * NKVH * HDIM];
__device__ __nv_bfloat16 g_at_h[S_LEN * DMODEL],        g_at_l[S_LEN * DMODEL];
__device__ __nv_bfloat16 g_x2_h[S_LEN * DMODEL],        g_x2_l[S_LEN * DMODEL];
__device__ __nv_bfloat16 g_ga_h[S_LEN * DFFN],          g_ga_l[S_LEN * DFFN];

// ================= RMSNorm -> bf16 hi/lo =================
__global__ __launch_bounds__(256) void rmsnorm_split_kernel(
    const float* __restrict__ x, const float* __restrict__ w,
    __nv_bfloat16* __restrict__ yh, __nv_bfloat16* __restrict__ yl)
{
    int row = blockIdx.x;
    const float* xr = x + (size_t)row * DMODEL;

    float4 vals[4];
    float ss = 0.f;
#pragma unroll
    for (int it = 0; it < 4; it++) {
        int idx = (threadIdx.x + it * 256) * 4;
        float4 v = *(const float4*)(xr + idx);
        vals[it] = v;
        ss += v.x*v.x + v.y*v.y + v.z*v.z + v.w*v.w;
    }
#pragma unroll
    for (int o = 16; o; o >>= 1) ss += __shfl_xor_sync(0xffffffffu, ss, o);

    __shared__ float red[8];
    if ((threadIdx.x & 31) == 0) red[threadIdx.x >> 5] = ss;
    __syncthreads();
    float tot = 0.f;
#pragma unroll
    for (int i = 0; i < 8; i++) tot += red[i];
    float inv = rsqrtf(tot * (1.f / DMODEL) + 1e-5f);

#pragma unroll
    for (int it = 0; it < 4; it++) {
        int idx = (threadIdx.x + it * 256) * 4;
        float4 v  = vals[it];
        float4 wv = *(const float4*)(w + idx);
        float r0 = v.x * inv * wv.x, r1 = v.y * inv * wv.y;
        float r2 = v.z * inv * wv.z, r3 = v.w * inv * wv.w;
        uint2 hv, lv;
        split2(r0, r1, hv.x, lv.x);
        split2(r2, r3, hv.y, lv.y);
        *(uint2*)(yh + (size_t)row * DMODEL + idx) = hv;
        *(uint2*)(yl + (size_t)row * DMODEL + idx) = lv;
    }
}

// ================= RoPE + L2-norm -> bf16 hi/lo =================
__global__ __launch_bounds__(256) void rope_l2_split_kernel(
    const float* __restrict__ in, __nv_bfloat16* __restrict__ outh, __nv_bfloat16* __restrict__ outl,
    int nheads, const float* __restrict__ cosb, const float* __restrict__ sinb, float scale)
{
    int wid  = (blockIdx.x * 256 + threadIdx.x) >> 5;
    int lane = threadIdx.x & 31;
    int s  = wid / nheads;
    int hh = wid % nheads;
    size_t base = (size_t)s * nheads * HDIM + hh * HDIM + lane * 4;
    float4 vv = *(const float4*)(in + base);

    float c0 = cosb[s * 64 + lane * 2],     s0 = sinb[s * 64 + lane * 2];
    float c1 = cosb[s * 64 + lane * 2 + 1], s1 = sinb[s * 64 + lane * 2 + 1];
    float o0 = vv.x * c0 - vv.y * s0;
    float o1 = vv.x * s0 + vv.y * c0;
    float o2 = vv.z * c1 - vv.w * s1;
    float o3 = vv.z * s1 + vv.w * c1;

    float ss = o0*o0 + o1*o1 + o2*o2 + o3*o3;
#pragma unroll
    for (int o = 16; o; o >>= 1) ss += __shfl_xor_sync(0xffffffffu, ss, o);
    float rr = rsqrtf(ss * (1.f / HDIM) + 1e-5f) * scale;
    o0 *= rr; o1 *= rr; o2 *= rr; o3 *= rr;

    uint2 hv, lv;
    split2(o0, o1, hv.x, lv.x);
    split2(o2, o3, hv.y, lv.y);
    *(uint2*)(outh + base) = hv;
    *(uint2*)(outl + base) = lv;
}

// ================= transpose + bf16 hi/lo split: in[K,N] fp32 -> hi/lo [N,K] bf16 =================
__global__ __launch_bounds__(256) void transpose_split_kernel(
    const float* __restrict__ in, __nv_bfloat16* __restrict__ hi, __nv_bfloat16* __restrict__ lo,
    int K, int N)
{
    __shared__ float s[64][65];
    int r0 = blockIdx.y * 64, c0 = blockIdx.x * 64;
#pragma unroll
    for (int i = 0; i < 16; i++) {
        int idx = threadIdx.x + i * 256;
        int lr = idx >> 6, lc = idx & 63;
        s[lr][lc] = in[(size_t)(r0 + lr) * N + c0 + lc];
    }
    __syncthreads();
#pragma unroll
    for (int i = 0; i < 16; i++) {
        int idx = threadIdx.x + i * 256;
        int lr = idx >> 6, lc = idx & 63;
        float v = s[lc][lr];
        __nv_bfloat16 h = __float2bfloat16(v);
        __nv_bfloat16 l = __float2bfloat16(v - __bfloat162float(h));
        size_t o = (size_t)(c0 + lr) * K + (r0 + lc);
        hi[o] = h; lo[o] = l;
    }
}

// ================= HMMA split-bf16 GEMM =================
// C[M,N] = A[M,K] @ B^T[N,K] (3-term hi/lo), optional fp32 out (+addend) and/or bf16 hi/lo out.
#define TCG_STAGE_BYTES 65536
#define TCG_NSTAGE 3
#define TCG_SMEM (TCG_NSTAGE * TCG_STAGE_BYTES)

__global__ __launch_bounds__(256, 1) void tc_gemm_kernel(
    const __nv_bfloat16* __restrict__ Ahi, const __nv_bfloat16* __restrict__ Alo,
    const __nv_bfloat16* __restrict__ Bhi, const __nv_bfloat16* __restrict__ Blo,
    float* __restrict__ C, const float* __restrict__ addend,
    __nv_bfloat16* __restrict__ outHi, __nv_bfloat16* __restrict__ outLo,
    int M, int N, int K)
{
    extern __shared__ char sm[];
    uint32_t sbase = smem_u32(sm);
    int tid = threadIdx.x, lane = tid & 31, wid = tid >> 5;
    int warp_m = wid & 1, warp_n = wid >> 1;
    int bx = blockIdx.x, by = blockIdx.y;

    const __nv_bfloat16* srcA[2] = { Ahi + (size_t)(by * 128) * K, Alo + (size_t)(by * 128) * K };
    const __nv_bfloat16* srcB[2] = { Bhi + (size_t)(bx * 128) * K, Blo + (size_t)(bx * 128) * K };

    int nchunk = K >> 6;
    int ldrow = tid >> 3;
    int ldc16 = tid & 7;

    auto load_stage = [&](int stg, int c) {
        uint32_t dst0 = sbase + stg * TCG_STAGE_BYTES;
        int kc = c << 6;
#pragma unroll
        for (int hl = 0; hl < 2; hl++) {
            const __nv_bfloat16* sa = srcA[hl] + kc;
            const __nv_bfloat16* sb = srcB[hl] + kc;
            uint32_t da = dst0 + hl * 16384;
            uint32_t db = dst0 + 32768 + hl * 16384;
#pragma unroll
            for (int i = 0; i < 4; i++) {
                int row = ldrow + i * 32;
                uint32_t sw = row * 128 + ((ldc16 ^ (row & 7)) << 4);
                cp_async16(da + sw, sa + (size_t)row * K + ldc16 * 8);
                cp_async16(db + sw, sb + (size_t)row * K + ldc16 * 8);
            }
        }
    };

    load_stage(0, 0); CP_COMMIT();
    load_stage(1, 1); CP_COMMIT();

    float acc[4][4][4];
#pragma unroll
    for (int a = 0; a < 4; a++)
#pragma unroll
        for (int b = 0; b < 4; b++)
#pragma unroll
            for (int f = 0; f < 4; f++) acc[a][b][f] = 0.f;

    int a_r   = warp_m * 64 + (lane & 15);
    int a_kh  = lane >> 4;
    int b_r   = warp_n * 32 + (lane & 7) + ((lane >> 4) << 3);
    int b_kh  = (lane >> 3) & 1;

    for (int c = 0; c < nchunk; c++) {
        CP_WAIT1();
        __syncthreads();
        if (c + 2 < nchunk) load_stage((c + 2) % TCG_NSTAGE, c + 2);
        CP_COMMIT();

        uint32_t st = sbase + (c % TCG_NSTAGE) * TCG_STAGE_BYTES;
#pragma unroll
        for (int kk = 0; kk < 4; kk++) {
            int c16 = kk * 2;
            uint32_t ah[4][4], al[4][4], bh[2][4], bl[2][4];
#pragma unroll
            for (int mb = 0; mb < 4; mb++) {
                int r = a_r + mb * 16;
                uint32_t off = r * 128 + (((c16 + a_kh) ^ (r & 7)) << 4);
                ldsm4(ah[mb], st + off);
                ldsm4(al[mb], st + 16384 + off);
            }
#pragma unroll
            for (int nb = 0; nb < 2; nb++) {
                int r = b_r + nb * 16;
                uint32_t off = r * 128 + (((c16 + b_kh) ^ (r & 7)) << 4);
                ldsm4(bh[nb], st + 32768 + off);
                ldsm4(bl[nb], st + 49152 + off);
            }
#pragma unroll
            for (int mb = 0; mb < 4; mb++)
#pragma unroll
                for (int nb = 0; nb < 4; nb++) {
                    uint32_t b0h = bh[nb >> 1][(nb & 1) * 2], b1h = bh[nb >> 1][(nb & 1) * 2 + 1];
                    uint32_t b0l = bl[nb >> 1][(nb & 1) * 2], b1l = bl[nb >> 1][(nb & 1) * 2 + 1];
                    mma16816(acc[mb][nb], ah[mb], b0h, b1h);
                    mma16816(acc[mb][nb], ah[mb], b0l, b1l);
                    mma16816(acc[mb][nb], al[mb], b0h, b1h);
                }
        }
        __syncthreads();
    }

#pragma unroll
    for (int mb = 0; mb < 4; mb++) {
        int mrow = by * 128 + warp_m * 64 + mb * 16 + (lane >> 2);
#pragma unroll
        for (int nb = 0; nb < 4; nb++) {
            int ncol = bx * 128 + warp_n * 32 + nb * 8 + (lane & 3) * 2;
            size_t i0 = (size_t)mrow * N + ncol;
            size_t i1 = (size_t)(mrow + 8) * N + ncol;
            float2 r0 = make_float2(acc[mb][nb][0], acc[mb][nb][1]);
            float2 r1 = make_float2(acc[mb][nb][2], acc[mb][nb][3]);
            if (addend) {
                float2 a0 = *(const float2*)(addend + i0);
                float2 a1 = *(const float2*)(addend + i1);
                r0.x += a0.x; r0.y += a0.y;
                r1.x += a1.x; r1.y += a1.y;
            }
            if (C) {
                *(float2*)(C + i0) = r0;
                *(float2*)(C + i1) = r1;
            }
            if (outHi) {
                uint32_t h0, l0, h1, l1;
                split2(r0.x, r0.y, h0, l0);
                split2(r1.x, r1.y, h1, l1);
                *(uint32_t*)(outHi + i0) = h0;
                *(uint32_t*)(outLo + i0) = l0;
                *(uint32_t*)(outHi + i1) = h1;
                *(uint32_t*)(outLo + i1) = l1;
            }
        }
    }
}

// ================= HMMA causal flash attention, GQA, split-bf16 =================
// BQ=BK=64, 4 warps (16 q-rows each), double-buffered cp.async K/V.
#define FA_STAGE_OFF 32768
#define FA_STAGE_BYTES 65536
#define FA_SMEM (FA_STAGE_OFF + 2 * FA_STAGE_BYTES)   // 160KB

__global__ __launch_bounds__(128, 1) void flash_attn_kernel(
    const __nv_bfloat16* __restrict__ qh, const __nv_bfloat16* __restrict__ ql,
    const __nv_bfloat16* __restrict__ kh, const __nv_bfloat16* __restrict__ kl,
    const __nv_bfloat16* __restrict__ vh, const __nv_bfloat16* __restrict__ vl,
    __nv_bfloat16* __restrict__ oh, __nv_bfloat16* __restrict__ ol)
{
    extern __shared__ char sm[];
    uint32_t sbase = smem_u32(sm);
    int qb = blockIdx.x, h = blockIdx.y, kvh = h >> 2;
    int tid = threadIdx.x, lane = tid & 31, w = tid >> 5;

    // Q (hi,lo) load: 2 x 16KB
#pragma unroll
    for (int i = 0; i < 8; i++) {
        int u = tid + i * 128;
        int row = u >> 4, c16 = u & 15;
        uint32_t dst = sbase + row * 256 + ((c16 ^ (row & 7)) << 4);
        size_t srco = (size_t)(qb * 64 + row) * DMODEL + h * HDIM + c16 * 8;
        cp_async16(dst,         qh + srco);
        cp_async16(dst + 16384, ql + srco);
    }

    auto load_kv = [&](int stg, int kb) {
        uint32_t dst0 = sbase + FA_STAGE_OFF + stg * FA_STAGE_BYTES;
        const __nv_bfloat16* srcs[4] = { kh, kl, vh, vl };
#pragma unroll
        for (int b = 0; b < 4; b++) {
            const __nv_bfloat16* s = srcs[b];
#pragma unroll
            for (int i = 0; i < 8; i++) {
                int u = tid + i * 128;
                int row = u >> 4, c16 = u & 15;
                uint32_t dst = dst0 + b * 16384 + row * 256 + ((c16 ^ (row & 7)) << 4);
                cp_async16(dst, s + (size_t)(kb * 64 + row) * (NKVH * HDIM) + kvh * HDIM + c16 * 8);
            }
        }
    };

    load_kv(0, 0); CP_COMMIT();
    if (qb >= 1) load_kv(1, 1);
    CP_COMMIT();

    float O[16][4];
#pragma unroll
    for (int i = 0; i < 16; i++)
#pragma unroll
        for (int f = 0; f < 4; f++) O[i][f] = 0.f;
    float m_lo = -1e30f, m_hi = -1e30f, l_lo = 0.f, l_hi = 0.f;

    int r_loc = w * 16 + (lane >> 2);   // local q row (lo); hi = +8

    for (int kb = 0; kb <= qb; kb++) {
        CP_WAIT1();
        __syncthreads();
        uint32_t kbase = sbase + FA_STAGE_OFF + (kb & 1) * FA_STAGE_BYTES;

        // ---- S = Q K^T (3-term split) ----
        float S[8][4];
#pragma unroll
        for (int i = 0; i < 8; i++)
#pragma unroll
            for (int f = 0; f < 4; f++) S[i][f] = 0.f;

#pragma unroll
        for (int kk = 0; kk < 8; kk++) {
            uint32_t aqh[4], aql[4];
            int ar = w * 16 + (lane & 15);
            int ac = kk * 2 + (lane >> 4);
            uint32_t aoff = ar * 256 + ((ac ^ (ar & 7)) << 4);
            ldsm4(aqh, sbase + aoff);
            ldsm4(aql, sbase + 16384 + aoff);
#pragma unroll
            for (int nblk = 0; nblk < 4; nblk++) {
                int br = nblk * 16 + (lane & 7) + ((lane >> 4) << 3);
                int bc = kk * 2 + ((lane >> 3) & 1);
                uint32_t boff = br * 256 + ((bc ^ (br & 7)) << 4);
                uint32_t bh4[4], bl4[4];
                ldsm4(bh4, kbase + boff);
                ldsm4(bl4, kbase + 16384 + boff);
                mma16816(S[2*nblk],   aqh, bh4[0], bh4[1]);
                mma16816(S[2*nblk],   aqh, bl4[0], bl4[1]);
                mma16816(S[2*nblk],   aql, bh4[0], bh4[1]);
                mma16816(S[2*nblk+1], aqh, bh4[2], bh4[3]);
                mma16816(S[2*nblk+1], aqh, bl4[2], bl4[3]);
                mma16816(S[2*nblk+1], aql, bh4[2], bh4[3]);
            }
        }

        // ---- causal mask on diagonal tile ----
        if (kb == qb) {
#pragma unroll
            for (int nt = 0; nt < 8; nt++) {
                int c = nt * 8 + (lane & 3) * 2;
                if (c     > r_loc)     S[nt][0] = -1e30f;
                if (c + 1 > r_loc)     S[nt][1] = -1e30f;
                if (c     > r_loc + 8) S[nt][2] = -1e30f;
                if (c + 1 > r_loc + 8) S[nt][3] = -1e30f;
            }
        }

        // ---- online softmax ----
        float rm_lo = -1e30f, rm_hi = -1e30f;
#pragma unroll
        for (int nt = 0; nt < 8; nt++) {
            rm_lo = fmaxf(rm_lo, fmaxf(S[nt][0], S[nt][1]));
            rm_hi = fmaxf(rm_hi, fmaxf(S[nt][2], S[nt][3]));
        }
        rm_lo = fmaxf(rm_lo, __shfl_xor_sync(0xffffffffu, rm_lo, 1));
        rm_lo = fmaxf(rm_lo, __shfl_xor_sync(0xffffffffu, rm_lo, 2));
        rm_hi = fmaxf(rm_hi, __shfl_xor_sync(0xffffffffu, rm_hi, 1));
        rm_hi = fmaxf(rm_hi, __shfl_xor_sync(0xffffffffu, rm_hi, 2));
        float mn_lo = fmaxf(m_lo, rm_lo), mn_hi = fmaxf(m_hi, rm_hi);
        float corr_lo = __expf(m_lo - mn_lo), corr_hi = __expf(m_hi - mn_hi);

        uint32_t ph[8][2], pl[8][2];
        float sum_lo = 0.f, sum_hi = 0.f;
#pragma unroll
        for (int nt = 0; nt < 8; nt++) {
            float p0 = __expf(S[nt][0] - mn_lo);
            float p1 = __expf(S[nt][1] - mn_lo);
            float p2 = __expf(S[nt][2] - mn_hi);
            float p3 = __expf(S[nt][3] - mn_hi);
            sum_lo += p0 + p1; sum_hi += p2 + p3;
            split2(p0, p1, ph[nt][0], pl[nt][0]);
            split2(p2, p3, ph[nt][1], pl[nt][1]);
        }
        sum_lo += __shfl_xor_sync(0xffffffffu, sum_lo, 1);
        sum_lo += __shfl_xor_sync(0xffffffffu, sum_lo, 2);
        sum_hi += __shfl_xor_sync(0xffffffffu, sum_hi, 1);
        sum_hi += __shfl_xor_sync(0xffffffffu, sum_hi, 2);
        l_lo = l_lo * corr_lo + sum_lo;
        l_hi = l_hi * corr_hi + sum_hi;
        m_lo = mn_lo; m_hi = mn_hi;
#pragma unroll
        for (int ot = 0; ot < 16; ot++) {
            O[ot][0] *= corr_lo; O[ot][1] *= corr_lo;
            O[ot][2] *= corr_hi; O[ot][3] *= corr_hi;
        }

        // ---- O += P V (3-term split) ----
        uint32_t vbase = kbase + 32768;
#pragma unroll
        for (int kt = 0; kt < 4; kt++) {
            uint32_t aH[4] = { ph[2*kt][0], ph[2*kt][1], ph[2*kt+1][0], ph[2*kt+1][1] };
            uint32_t aL[4] = { pl[2*kt][0], pl[2*kt][1], pl[2*kt+1][0], pl[2*kt+1][1] };
            int krow = kt * 16 + (lane & 7) + ((lane >> 3) & 1) * 8;
#pragma unroll
            for (int ob = 0; ob < 8; ob++) {
                int cu = ob * 2 + (lane >> 4);
                uint32_t off = krow * 256 + ((cu ^ (krow & 7)) << 4);
                uint32_t bvh[4], bvl[4];
                ldsm4t(bvh, vbase + off);
                ldsm4t(bvl, vbase + 16384 + off);
                mma16816(O[2*ob],   aH, bvh[0], bvh[1]);
                mma16816(O[2*ob],   aH, bvl[0], bvl[1]);
                mma16816(O[2*ob],   aL, bvh[0], bvh[1]);
                mma16816(O[2*ob+1], aH, bvh[2], bvh[3]);
                mma16816(O[2*ob+1], aH, bvl[2], bvl[3]);
                mma16816(O[2*ob+1], aL, bvh[2], bvh[3]);
            }
        }

        __syncthreads();
        if (kb + 2 <= qb) load_kv(kb & 1, kb + 2);
        CP_COMMIT();
    }

    // ---- epilogue: normalize, split to bf16 hi/lo ----
    float il_lo = 1.f / l_lo, il_hi = 1.f / l_hi;
    int row0 = qb * 64 + r_loc;
#pragma unroll
    for (int ot = 0; ot < 16; ot++) {
        int col = h * HDIM + ot * 8 + (lane & 3) * 2;
        float o0 = O[ot][0] * il_lo, o1 = O[ot][1] * il_lo;
        float o2 = O[ot][2] * il_hi, o3 = O[ot][3] * il_hi;
        uint32_t h0, l0, h1, l1;
        split2(o0, o1, h0, l0);
        split2(o2, o3, h1, l1);
        size_t i0 = (size_t)row0 * DMODEL + col;
        size_t i1 = (size_t)(row0 + 8) * DMODEL + col;
        *(uint32_t*)(oh + i0) = h0;
        *(uint32_t*)(ol + i0) = l0;
        *(uint32_t*)(oh + i1) = h1;
        *(uint32_t*)(ol + i1) = l1;
    }
}

// ================= SiLU(gate)*up -> bf16 hi/lo =================
__global__ __launch_bounds__(256) void silu_mul_split_kernel(
    const float* __restrict__ gate, const float* __restrict__ up,
    __nv_bfloat16* __restrict__ yh, __nv_bfloat16* __restrict__ yl)
{
    size_t i = (size_t)blockIdx.x * 256 + threadIdx.x;
    float4 gv = ((const float4*)gate)[i];
    float4 uv = ((const float4*)up)[i];
    float r0 = gv.x / (1.f + __expf(-gv.x)) * uv.x;
    float r1 = gv.y / (1.f + __expf(-gv.y)) * uv.y;
    float r2 = gv.z / (1.f + __expf(-gv.z)) * uv.z;
    float r3 = gv.w / (1.f + __expf(-gv.w)) * uv.w;
    uint2 hv, lv;
    split2(r0, r1, hv.x, lv.x);
    split2(r2, r3, hv.y, lv.y);
    ((uint2*)yh)[i] = hv;
    ((uint2*)yl)[i] = lv;
}

// ================= host launcher =================
extern "C" void kernel_launch(void* const* d_in, const int* in_sizes, int n_in,
                              void* d_out, int out_size)
{
    const float* hidden = (const float*)d_in[0];
    const float* cosb  = (const float*)d_in[2];
    const float* sinb  = (const float*)d_in[3];
    const float* ln1   = (const float*)d_in[4];
    const float* wq    = (const float*)d_in[5];
    const float* wk    = (const float*)d_in[6];
    const float* wv    = (const float*)d_in[7];
    const float* wo    = (const float*)d_in[8];
    const float* ln2   = (const float*)d_in[9];
    const float* gatew = (const float*)d_in[10];
    const float* upw   = (const float*)d_in[11];
    const float* downw = (const float*)d_in[12];
    float* out = (float*)d_out;

    float *q, *k, *h, *gate, *up;
    cudaGetSymbolAddress((void**)&q,    g_q);
    cudaGetSymbolAddress((void**)&k,    g_k);
    cudaGetSymbolAddress((void**)&h,    g_h);
    cudaGetSymbolAddress((void**)&gate, g_gate);
    cudaGetSymbolAddress((void**)&up,   g_up);

    __nv_bfloat16 *wqTh,*wqTl,*wkTh,*wkTl,*wvTh,*wvTl,*woTh,*woTl,*gwTh,*gwTl,*uwTh,*uwTl,*dwTh,*dwTl;
    cudaGetSymbolAddress((void**)&wqTh, g_wqT_h); cudaGetSymbolAddress((void**)&wqTl, g_wqT_l);
    cudaGetSymbolAddress((void**)&wkTh, g_wkT_h); cudaGetSymbolAddress((void**)&wkTl, g_wkT_l);
    cudaGetSymbolAddress((void**)&wvTh, g_wvT_h); cudaGetSymbolAddress((void**)&wvTl, g_wvT_l);
    cudaGetSymbolAddress((void**)&woTh, g_woT_h); cudaGetSymbolAddress((void**)&woTl, g_woT_l);
    cudaGetSymbolAddress((void**)&gwTh, g_gwT_h); cudaGetSymbolAddress((void**)&gwTl, g_gwT_l);
    cudaGetSymbolAddress((void**)&uwTh, g_uwT_h); cudaGetSymbolAddress((void**)&uwTl, g_uwT_l);
    cudaGetSymbolAddress((void**)&dwTh, g_dwT_h); cudaGetSymbolAddress((void**)&dwTl, g_dwT_l);

    __nv_bfloat16 *xnh,*xnl,*qhp,*qlp,*khp,*klp,*vhp,*vlp,*ath,*atl,*x2h,*x2l,*gah,*gal;
    cudaGetSymbolAddress((void**)&xnh, g_xn_h); cudaGetSymbolAddress((void**)&xnl, g_xn_l);
    cudaGetSymbolAddress((void**)&qhp, g_qh);   cudaGetSymbolAddress((void**)&qlp, g_ql);
    cudaGetSymbolAddress((void**)&khp, g_kh);   cudaGetSymbolAddress((void**)&klp, g_kl);
    cudaGetSymbolAddress((void**)&vhp, g_vh);   cudaGetSymbolAddress((void**)&vlp, g_vl);
    cudaGetSymbolAddress((void**)&ath, g_at_h); cudaGetSymbolAddress((void**)&atl, g_at_l);
    cudaGetSymbolAddress((void**)&x2h, g_x2_h); cudaGetSymbolAddress((void**)&x2l, g_x2_l);
    cudaGetSymbolAddress((void**)&gah, g_ga_h); cudaGetSymbolAddress((void**)&gal, g_ga_l);

    cudaFuncSetAttribute(tc_gemm_kernel, cudaFuncAttributeMaxDynamicSharedMemorySize, TCG_SMEM);
    cudaFuncSetAttribute(flash_attn_kernel, cudaFuncAttributeMaxDynamicSharedMemorySize, FA_SMEM);

    // ---- weight transposes + hi/lo splits ----
    transpose_split_kernel<<<dim3(DMODEL/64, DMODEL/64), 256>>>(wq, wqTh, wqTl, DMODEL, DMODEL);
    transpose_split_kernel<<<dim3(NKVH*HDIM/64, DMODEL/64), 256>>>(wk, wkTh, wkTl, DMODEL, NKVH*HDIM);
    transpose_split_kernel<<<dim3(NKVH*HDIM/64, DMODEL/64), 256>>>(wv, wvTh, wvTl, DMODEL, NKVH*HDIM);
    transpose_split_kernel<<<dim3(DMODEL/64, DMODEL/64), 256>>>(wo, woTh, woTl, DMODEL, DMODEL);
    transpose_split_kernel<<<dim3(DFFN/64, DMODEL/64), 256>>>(gatew, gwTh, gwTl, DMODEL, DFFN);
    transpose_split_kernel<<<dim3(DFFN/64, DMODEL/64), 256>>>(upw,   uwTh, uwTl, DMODEL, DFFN);
    transpose_split_kernel<<<dim3(DMODEL/64, DFFN/64), 256>>>(downw, dwTh, dwTl, DFFN, DMODEL);

    // 1) x = rmsnorm(hidden, ln1) -> bf16 hi/lo
    rmsnorm_split_kernel<<<S_LEN, 256>>>(hidden, ln1, xnh, xnl);

    // 2) q/k fp32 (for rope); v -> bf16 hi/lo directly
    tc_gemm_kernel<<<dim3(DMODEL/128, S_LEN/128), 256, TCG_SMEM>>>(xnh, xnl, wqTh, wqTl, q, nullptr, nullptr, nullptr, S_LEN, DMODEL, DMODEL);
    tc_gemm_kernel<<<dim3(NKVH*HDIM/128, S_LEN/128), 256, TCG_SMEM>>>(xnh, xnl, wkTh, wkTl, k, nullptr, nullptr, nullptr, S_LEN, NKVH*HDIM, DMODEL);
    tc_gemm_kernel<<<dim3(NKVH*HDIM/128, S_LEN/128), 256, TCG_SMEM>>>(xnh, xnl, wvTh, wvTl, nullptr, nullptr, vhp, vlp, S_LEN, NKVH*HDIM, DMODEL);

    // 3) RoPE + L2-norm -> bf16 hi/lo; fold HD^-0.5 into q
    const float qscale = 0.08838834764831845f;
    rope_l2_split_kernel<<<S_LEN * NHEADS / 8, 256>>>(q, qhp, qlp, NHEADS, cosb, sinb, qscale);
    rope_l2_split_kernel<<<S_LEN * NKVH  / 8, 256>>>(k, khp, klp, NKVH,  cosb, sinb, 1.f);

    // 4) HMMA causal flash attention -> attn bf16 hi/lo
    flash_attn_kernel<<<dim3(S_LEN / 64, NHEADS), 128, FA_SMEM>>>(qhp, qlp, khp, klp, vhp, vlp, ath, atl);

    // 5) h = hidden + attn @ wo (fp32)
    tc_gemm_kernel<<<dim3(DMODEL/128, S_LEN/128), 256, TCG_SMEM>>>(ath, atl, woTh, woTl, h, hidden, nullptr, nullptr, S_LEN, DMODEL, DMODEL);

    // 6) x2 = rmsnorm(h, ln2) -> bf16 hi/lo
    rmsnorm_split_kernel<<<S_LEN, 256>>>(h, ln2, x2h, x2l);

    // 7) FFN gate/up (fp32), silu*up -> bf16 hi/lo
    tc_gemm_kernel<<<dim3(DFFN/128, S_LEN/128), 256, TCG_SMEM>>>(x2h, x2l, gwTh, gwTl, gate, nullptr, nullptr, nullptr, S_LEN, DFFN, DMODEL);
    tc_gemm_kernel<<<dim3(DFFN/128, S_LEN/128), 256, TCG_SMEM>>>(x2h, x2l, uwTh, uwTl, up,   nullptr, nullptr, nullptr, S_LEN, DFFN, DMODEL);
    silu_mul_split_kernel<<<(S_LEN * DFFN) / 4 / 256, 256>>>(gate, up, gah, gal);

    // 8) out = h + act @ down
    tc_gemm_kernel<<<dim3(DMODEL/128, S_LEN/128), 256, TCG_SMEM>>>(gah, gal, dwTh, dwTl, out, h, nullptr, nullptr, S_LEN, DMODEL, DFFN);
}